// round 12
// baseline (speedup 1.0000x reference)
#include <cuda_runtime.h>
#include <cstdint>
#include <math.h>

#define CC    768
#define C3    2304
#define C6    4608
#define HIDN  3072
#define NHEAD 12
#define HD    64
#define WSZ   8
#define SHF   4
#define LL    4096
#define MM    32768   // 512 windows * 64 tokens  == 8 * 4096

// ---------------- scratch (device globals; no cudaMalloc allowed) ----------------
__device__ float g_mod[8 * C6];                    // adaLN modulation, (B, 6C)
__device__ float g_win[(size_t)MM * CC];           // windowed, modulated LN(x)
__device__ float g_qkv[(size_t)MM * C3];           // qkv
__device__ float g_attn[(size_t)MM * CC];          // attention output (window order)
__device__ float g_x1[(size_t)MM * CC];            // x + g_msa * proj (image order)
__device__ float g_h2[(size_t)MM * CC];            // modulated LN(x1)
__device__ float g_hid[(size_t)MM * HIDN];         // gelu(fc1)

// ---------------- packed fp32x2 helpers (sm_103a FFMA2) ----------------
__device__ __forceinline__ unsigned long long dupf2(float a) {
    unsigned long long r; unsigned int u = __float_as_uint(a);
    asm("mov.b64 %0, {%1, %1};" : "=l"(r) : "r"(u));
    return r;
}
__device__ __forceinline__ void fma_f32x2(unsigned long long& d,
                                          unsigned long long a,
                                          unsigned long long b) {
    asm("fma.rn.f32x2 %0, %1, %2, %0;" : "+l"(d) : "l"(a), "l"(b));
}
__device__ __forceinline__ float2 unpackf2(unsigned long long p) {
    unsigned int lo, hi;
    asm("mov.b64 {%0, %1}, %2;" : "=r"(lo), "=r"(hi) : "l"(p));
    return make_float2(__uint_as_float(lo), __uint_as_float(hi));
}

// ---------------- kernel 1: mod = silu(c) @ w_adaln + b_adaln ----------------
__global__ void __launch_bounds__(256) adaln_kernel(const float* __restrict__ c,
                                                    const float* __restrict__ w,
                                                    const float* __restrict__ bias) {
    __shared__ float sc[CC];
    int b = blockIdx.y;
    for (int k = threadIdx.x; k < CC; k += 256) {
        float v = c[b * CC + k];
        sc[k] = v / (1.0f + expf(-v));
    }
    __syncthreads();
    int j = blockIdx.x * 256 + threadIdx.x;   // 0..4607
    float acc = 0.f;
    #pragma unroll 4
    for (int k = 0; k < CC; k++) acc = fmaf(sc[k], w[(size_t)k * C6 + j], acc);
    g_mod[b * C6 + j] = acc + bias[j];
}

// ---------------- kernel 2/6: LayerNorm + modulate (+optional roll/window gather) ---
// WINDOWED=true : output row m indexes (window, token); source gathered from x with
//                 roll(-SHF) + window partition.  mod_off = 0 (MSA shift/scale).
// WINDOWED=false: identity row mapping (x1 -> h2).   mod_off = 2304 (MLP shift/scale).
template<bool WINDOWED>
__global__ void __launch_bounds__(256) ln_mod_kernel(const float* __restrict__ src,
                                                     float* __restrict__ dst,
                                                     int mod_off) {
    int m = blockIdx.x;
    int b, src_row;
    if (WINDOWED) {
        int widx = m >> 6, n = m & 63;
        b = widx >> 6;
        int wh = (widx >> 3) & 7, ww = widx & 7;
        int i = n >> 3, j = n & 7;
        int h = (wh * WSZ + i + SHF) & 63;
        int w = (ww * WSZ + j + SHF) & 63;
        src_row = b * LL + h * 64 + w;
    } else {
        b = m >> 12;
        src_row = m;
    }
    const float* xr = src + (size_t)src_row * CC;
    int t = threadIdx.x;
    float v[3]; float s1 = 0.f, s2 = 0.f;
    #pragma unroll
    for (int r = 0; r < 3; r++) {
        float x = xr[t + r * 256];
        v[r] = x; s1 += x; s2 += x * x;
    }
    #pragma unroll
    for (int o = 16; o; o >>= 1) {
        s1 += __shfl_xor_sync(0xffffffffu, s1, o);
        s2 += __shfl_xor_sync(0xffffffffu, s2, o);
    }
    __shared__ float r1[8], r2[8], st[2];
    if ((t & 31) == 0) { r1[t >> 5] = s1; r2[t >> 5] = s2; }
    __syncthreads();
    if (t == 0) {
        float a = 0.f, q = 0.f;
        #pragma unroll
        for (int i = 0; i < 8; i++) { a += r1[i]; q += r2[i]; }
        float mu  = a * (1.0f / CC);
        float var = q * (1.0f / CC) - mu * mu;
        st[0] = mu; st[1] = rsqrtf(var + 1e-6f);
    }
    __syncthreads();
    float mu = st[0], rsg = st[1];
    const float* shv = g_mod + b * C6 + mod_off;   // shift
    const float* scv = shv + CC;                   // scale
    float* dr = dst + (size_t)m * CC;
    #pragma unroll
    for (int r = 0; r < 3; r++) {
        int ch = t + r * 256;
        dr[ch] = (v[r] - mu) * rsg * (1.0f + scv[ch]) + shv[ch];
    }
}

// ---------------- generic 128x128x8 fp32x2 GEMM with fused epilogues ----------------
// EPI 0: + bias                                   (qkv)
// EPI 1: gelu(+bias)                              (fc1)
// EPI 2: x1[scatter] = res + g_msa * (+bias)      (proj; un-window + un-roll scatter)
// EPI 3: out       = res + g_mlp * (+bias)        (fc2)
template<int EPI>
__global__ void __launch_bounds__(256) gemm128(const float* __restrict__ A,
                                               const float* __restrict__ Bw,
                                               const float* __restrict__ bias,
                                               float* __restrict__ Cout,
                                               int K, int Nc,
                                               const float* __restrict__ res) {
    const int bm = blockIdx.y * 128;
    const int bn = blockIdx.x * 128;
    __shared__ __align__(16) float As[8][128];   // As[k][m]
    __shared__ __align__(16) float Bs[8][128];   // Bs[k][n]
    unsigned long long acc[8][4];
    #pragma unroll
    for (int i = 0; i < 8; i++)
        #pragma unroll
        for (int j = 0; j < 4; j++) acc[i][j] = 0ull;

    int t  = threadIdx.x;
    int ty = t >> 4, tx = t & 15;          // 16x16 threads, 8x8 microtile each
    int arow = t >> 1, acol = (t & 1) * 4; // A tile load: 128 rows x 8 k
    int brow = t >> 5, bcol = (t & 31) * 4;// B tile load: 8 k x 128 cols
    const float* Ap = A  + (size_t)(bm + arow) * K + acol;
    const float* Bp = Bw + (size_t)brow * Nc + bn + bcol;

    for (int k0 = 0; k0 < K; k0 += 8) {
        float4 av = *(const float4*)Ap;  Ap += 8;
        float4 bv = *(const float4*)Bp;  Bp += (size_t)8 * Nc;
        As[acol + 0][arow] = av.x;
        As[acol + 1][arow] = av.y;
        As[acol + 2][arow] = av.z;
        As[acol + 3][arow] = av.w;
        *(float4*)&Bs[brow][bcol] = bv;
        __syncthreads();
        #pragma unroll
        for (int kk = 0; kk < 8; kk++) {
            const float4 a0 = *(const float4*)&As[kk][ty * 8];
            const float4 a1 = *(const float4*)&As[kk][ty * 8 + 4];
            const unsigned long long* Bd =
                (const unsigned long long*)&Bs[kk][tx * 8];
            unsigned long long bq0 = Bd[0], bq1 = Bd[1], bq2 = Bd[2], bq3 = Bd[3];
            float ar[8] = {a0.x, a0.y, a0.z, a0.w, a1.x, a1.y, a1.z, a1.w};
            #pragma unroll
            for (int i = 0; i < 8; i++) {
                unsigned long long ap = dupf2(ar[i]);
                fma_f32x2(acc[i][0], ap, bq0);
                fma_f32x2(acc[i][1], ap, bq1);
                fma_f32x2(acc[i][2], ap, bq2);
                fma_f32x2(acc[i][3], ap, bq3);
            }
        }
        __syncthreads();
    }

    // ---- epilogue ----
    float bv8[8];
    #pragma unroll
    for (int j = 0; j < 8; j++) bv8[j] = bias[bn + tx * 8 + j];
    #pragma unroll
    for (int i = 0; i < 8; i++) {
        int gm = bm + ty * 8 + i;
        int out_row, b;
        if (EPI == 2) {
            int widx = gm >> 6, n = gm & 63;
            b = widx >> 6;
            int wh = (widx >> 3) & 7, ww = widx & 7;
            int ii = n >> 3, jj = n & 7;
            int h = (wh * WSZ + ii + SHF) & 63;
            int w = (ww * WSZ + jj + SHF) & 63;
            out_row = b * LL + h * 64 + w;
        } else {
            out_row = gm;
            b = gm >> 12;
        }
        #pragma unroll
        for (int j2 = 0; j2 < 4; j2++) {
            float2 p = unpackf2(acc[i][j2]);
            float vals[2] = {p.x, p.y};
            #pragma unroll
            for (int s = 0; s < 2; s++) {
                int j  = j2 * 2 + s;
                int gn = bn + tx * 8 + j;
                float val = vals[s] + bv8[j];
                if (EPI == 1)
                    val = 0.5f * val * (1.0f + erff(val * 0.70710678118654752f));
                if (EPI == 2)
                    val = res[(size_t)out_row * CC + gn] +
                          g_mod[b * C6 + 1536 + gn] * val;
                if (EPI == 3)
                    val = res[(size_t)out_row * CC + gn] +
                          g_mod[b * C6 + 3840 + gn] * val;
                Cout[(size_t)out_row * Nc + gn] = val;
            }
        }
    }
}

// ---------------- kernel 4: windowed attention, one block per (window, head) --------
// S = (q*0.125) @ k^T + rpb[rel] + mask[widx%64];  P = softmax(S);  O = P @ V
__global__ void __launch_bounds__(256) attn_kernel(const float* __restrict__ qkv,
                                                   const float* __restrict__ mask,
                                                   const int*   __restrict__ relidx,
                                                   const float* __restrict__ rpb,
                                                   float* __restrict__ out) {
    extern __shared__ float smx[];
    float* qs = smx;             // [64][65]  q (pre-scaled)
    float* kT = smx + 64 * 65;   // [64][65]  kT[d][c]
    float* vs = kT  + 64 * 65;   // [64][65]  v[c][d]
    float* ps = vs  + 64 * 65;   // [64][65]  scores / probs
    int widx = blockIdx.x, head = blockIdx.y;
    int t = threadIdx.x;
    const float* base = qkv + (size_t)widx * 64 * C3 + head * HD;
    for (int idx = t; idx < 4096; idx += 256) {
        int n = idx >> 6, d = idx & 63;
        const float* p = base + (size_t)n * C3 + d;
        qs[n * 65 + d] = p[0] * 0.125f;
        kT[d * 65 + n] = p[768];
        vs[n * 65 + d] = p[1536];
    }
    __syncthreads();

    int r = t >> 2, cp = (t & 3) * 16;     // each thread: row r, 16 columns
    float acc[16];
    #pragma unroll
    for (int j = 0; j < 16; j++) acc[j] = 0.f;
    #pragma unroll 4
    for (int d = 0; d < 64; d++) {
        float qv = qs[r * 65 + d];
        #pragma unroll
        for (int j = 0; j < 16; j++)
            acc[j] = fmaf(qv, kT[d * 65 + cp + j], acc[j]);
    }
    const float* mrow = mask + (size_t)(widx & 63) * 4096 + r * 64 + cp;
    const int*   rrow = relidx + r * 64 + cp;
    #pragma unroll
    for (int j = 0; j < 16; j++) {
        float bv = rpb[rrow[j] * NHEAD + head];
        ps[r * 65 + cp + j] = acc[j] + bv + mrow[j];
    }
    __syncthreads();

    int warp = t >> 5, lane = t & 31;
    for (int rr = warp; rr < 64; rr += 8) {
        float a0 = ps[rr * 65 + lane];
        float a1 = ps[rr * 65 + 32 + lane];
        float mx = fmaxf(a0, a1);
        #pragma unroll
        for (int o = 16; o; o >>= 1) mx = fmaxf(mx, __shfl_xor_sync(0xffffffffu, mx, o));
        float e0 = expf(a0 - mx), e1 = expf(a1 - mx);
        float s = e0 + e1;
        #pragma unroll
        for (int o = 16; o; o >>= 1) s += __shfl_xor_sync(0xffffffffu, s, o);
        float inv = 1.0f / s;
        ps[rr * 65 + lane]      = e0 * inv;
        ps[rr * 65 + 32 + lane] = e1 * inv;
    }
    __syncthreads();

    float oacc[16];
    #pragma unroll
    for (int j = 0; j < 16; j++) oacc[j] = 0.f;
    #pragma unroll 4
    for (int c = 0; c < 64; c++) {
        float p = ps[r * 65 + c];
        #pragma unroll
        for (int j = 0; j < 16; j++)
            oacc[j] = fmaf(p, vs[c * 65 + cp + j], oacc[j]);
    }
    float* orow = out + (size_t)(widx * 64 + r) * CC + head * HD + cp;
    #pragma unroll
    for (int j = 0; j < 16; j++) orow[j] = oacc[j];
}

// ---------------- host launcher ----------------
extern "C" void kernel_launch(void* const* d_in, const int* in_sizes, int n_in,
                              void* d_out, int out_size) {
    (void)in_sizes; (void)n_in; (void)out_size;
    const float* x       = (const float*)d_in[0];
    const float* c       = (const float*)d_in[1];
    const float* mask    = (const float*)d_in[2];
    const int*   relidx  = (const int*)  d_in[3];
    const float* w_adaln = (const float*)d_in[4];
    const float* b_adaln = (const float*)d_in[5];
    const float* w_qkv   = (const float*)d_in[6];
    const float* b_qkv   = (const float*)d_in[7];
    const float* rpb     = (const float*)d_in[8];
    const float* w_proj  = (const float*)d_in[9];
    const float* b_proj  = (const float*)d_in[10];
    const float* w_fc1   = (const float*)d_in[11];
    const float* b_fc1   = (const float*)d_in[12];
    const float* w_fc2   = (const float*)d_in[13];
    const float* b_fc2   = (const float*)d_in[14];
    float* out = (float*)d_out;

    float *win, *qkv, *attn, *x1, *h2, *hid;
    cudaGetSymbolAddress((void**)&win,  g_win);
    cudaGetSymbolAddress((void**)&qkv,  g_qkv);
    cudaGetSymbolAddress((void**)&attn, g_attn);
    cudaGetSymbolAddress((void**)&x1,   g_x1);
    cudaGetSymbolAddress((void**)&h2,   g_h2);
    cudaGetSymbolAddress((void**)&hid,  g_hid);

    // 1. adaLN modulation vectors
    adaln_kernel<<<dim3(C6 / 256, 8), 256>>>(c, w_adaln, b_adaln);
    // 2. LN + modulate + roll(-4,-4) + window partition
    ln_mod_kernel<true><<<MM, 256>>>(x, win, 0);
    // 3. QKV projection
    gemm128<0><<<dim3(C3 / 128, MM / 128), 256>>>(win, w_qkv, b_qkv, qkv, CC, C3, nullptr);
    // 4. windowed attention
    const int attn_smem = 4 * 64 * 65 * (int)sizeof(float);  // 66,560 B
    cudaFuncSetAttribute(attn_kernel, cudaFuncAttributeMaxDynamicSharedMemorySize, attn_smem);
    attn_kernel<<<dim3(512, NHEAD), 256, attn_smem>>>(qkv, mask, relidx, rpb, attn);
    // 5. output projection + un-window/un-roll scatter + gated residual -> x1
    gemm128<2><<<dim3(CC / 128, MM / 128), 256>>>(attn, w_proj, b_proj, x1, CC, CC, x);
    // 6. LN + modulate (MLP)
    ln_mod_kernel<false><<<MM, 256>>>(x1, h2, 3 * CC);
    // 7. fc1 + exact GELU
    gemm128<1><<<dim3(HIDN / 128, MM / 128), 256>>>(h2, w_fc1, b_fc1, hid, CC, HIDN, nullptr);
    // 8. fc2 + gated residual -> final output
    gemm128<3><<<dim3(CC / 128, MM / 128), 256>>>(hid, w_fc2, b_fc2, out, HIDN, CC, x1);
}